// round 1
// baseline (speedup 1.0000x reference)
#include <cuda_runtime.h>
#include <cuda_bf16.h>
#include <math.h>

// Problem constants (fixed by reference)
#define BB 8
#define NN 1024
#define DD 512
#define EE 8
#define NEGV (-1e9f)
#define SLOPE 0.2f

// ---------------------------------------------------------------------------
// Static device scratch (allocation-free rule: __device__ globals)
// ---------------------------------------------------------------------------
__device__ static float g_h[(size_t)BB * EE * NN * DD];     // 128 MB  h[b,e,n,z]
__device__ static float g_attn[(size_t)BB * EE * NN * NN];  // 256 MB  attn[b,e,i,j]
__device__ static float g_oute[(size_t)BB * EE * NN * DD];  // 128 MB  elu(attn@h)
__device__ static float g_gate[(size_t)BB * NN * EE];       // gate[b,n,e]
__device__ static float g_ssrc[(size_t)BB * EE * NN];
__device__ static float g_sdst[(size_t)BB * EE * NN];

// ---------------------------------------------------------------------------
// K1: gate = softmax(x @ gate_W + gate_b)  over E.  One warp per (b,n) row.
// ---------------------------------------------------------------------------
__global__ void k_gate(const float* __restrict__ X, const float* __restrict__ GW,
                       const float* __restrict__ GB) {
    int row = blockIdx.x * 8 + (threadIdx.x >> 5);  // (b*N + n)
    int lane = threadIdx.x & 31;
    if (row >= BB * NN) return;

    float acc[EE];
#pragma unroll
    for (int e = 0; e < EE; e++) acc[e] = 0.f;

    const float* xr = X + (size_t)row * DD;
    for (int d = lane; d < DD; d += 32) {
        float xv = xr[d];
        const float* gw = GW + (size_t)d * EE;
#pragma unroll
        for (int e = 0; e < EE; e++) acc[e] = fmaf(xv, gw[e], acc[e]);
    }
#pragma unroll
    for (int e = 0; e < EE; e++) {
#pragma unroll
        for (int off = 16; off > 0; off >>= 1)
            acc[e] += __shfl_xor_sync(0xFFFFFFFFu, acc[e], off);
    }
    if (lane == 0) {
        float m = -3.4e38f;
#pragma unroll
        for (int e = 0; e < EE; e++) { acc[e] += GB[e]; m = fmaxf(m, acc[e]); }
        float s = 0.f;
#pragma unroll
        for (int e = 0; e < EE; e++) { acc[e] = expf(acc[e] - m); s += acc[e]; }
        float inv = 1.0f / s;
        float* gr = g_gate + (size_t)row * EE;
#pragma unroll
        for (int e = 0; e < EE; e++) gr[e] = acc[e] * inv;
    }
}

// ---------------------------------------------------------------------------
// Tiled fp32 GEMM, 128x128x16 tiles, 8x8 per thread, 256 threads.
// MODE 0: h-GEMM  C = x[b] @ W[e]          (M=1024, Nn=512, K=512)  -> g_h
// MODE 1: out-GEMM C = elu(attn[be] @ h[be]) (M=1024, Nn=512, K=1024) -> g_oute
// grid: (Nn/128, M/128, B*E)
// ---------------------------------------------------------------------------
template <int MODE>
__global__ void __launch_bounds__(256) k_sgemm(const float* __restrict__ X,
                                               const float* __restrict__ W) {
    constexpr int K = (MODE == 0) ? DD : NN;
    constexpr int LDB = DD;   // W: D x D;  h: N x D
    constexpr int LDC = DD;

    const int bz = blockIdx.z;            // be = b*E + e
    const float* Ab;
    const float* Bb;
    float* Cb;
    if (MODE == 0) {
        Ab = X + (size_t)(bz >> 3) * NN * DD;       // x[b]
        Bb = W + (size_t)(bz & 7) * DD * DD;        // W[e]
        Cb = g_h + (size_t)bz * NN * DD;
    } else {
        Ab = g_attn + (size_t)bz * NN * NN;
        Bb = g_h + (size_t)bz * NN * DD;
        Cb = g_oute + (size_t)bz * NN * DD;
    }

    __shared__ float As[16][132];
    __shared__ float Bs[16][132];

    const int tid = threadIdx.x;
    const int tx = tid & 15;
    const int ty = tid >> 4;
    const int rowBase = blockIdx.y * 128;
    const int colBase = blockIdx.x * 128;

    float acc[8][8];
#pragma unroll
    for (int i = 0; i < 8; i++)
#pragma unroll
        for (int j = 0; j < 8; j++) acc[i][j] = 0.f;

    for (int k0 = 0; k0 < K; k0 += 16) {
        // load A tile (128 rows x 16 cols) -> transposed into As[k][row]
#pragma unroll
        for (int l = 0; l < 2; l++) {
            int idx = tid + l * 256;             // 512 float4 total
            int r = idx >> 2;
            int c4 = (idx & 3) * 4;
            float4 v = *reinterpret_cast<const float4*>(
                Ab + (size_t)(rowBase + r) * K + k0 + c4);
            As[c4 + 0][r] = v.x;
            As[c4 + 1][r] = v.y;
            As[c4 + 2][r] = v.z;
            As[c4 + 3][r] = v.w;
        }
        // load B tile (16 rows x 128 cols) -> Bs[k][col]
#pragma unroll
        for (int l = 0; l < 2; l++) {
            int idx = tid + l * 256;
            int r = idx >> 5;
            int c = (idx & 31) * 4;
            float4 v = *reinterpret_cast<const float4*>(
                Bb + (size_t)(k0 + r) * LDB + colBase + c);
            *reinterpret_cast<float4*>(&Bs[r][c]) = v;
        }
        __syncthreads();

#pragma unroll
        for (int k = 0; k < 16; k++) {
            float4 a0 = *reinterpret_cast<const float4*>(&As[k][ty * 8]);
            float4 a1 = *reinterpret_cast<const float4*>(&As[k][ty * 8 + 4]);
            float4 b0 = *reinterpret_cast<const float4*>(&Bs[k][tx * 8]);
            float4 b1 = *reinterpret_cast<const float4*>(&Bs[k][tx * 8 + 4]);
            float ar[8] = {a0.x, a0.y, a0.z, a0.w, a1.x, a1.y, a1.z, a1.w};
            float br[8] = {b0.x, b0.y, b0.z, b0.w, b1.x, b1.y, b1.z, b1.w};
#pragma unroll
            for (int i = 0; i < 8; i++)
#pragma unroll
                for (int j = 0; j < 8; j++)
                    acc[i][j] = fmaf(ar[i], br[j], acc[i][j]);
        }
        __syncthreads();
    }

    // epilogue
#pragma unroll
    for (int i = 0; i < 8; i++) {
        int r = rowBase + ty * 8 + i;
        float* crow = Cb + (size_t)r * LDC + colBase + tx * 8;
#pragma unroll
        for (int j4 = 0; j4 < 2; j4++) {
            float4 v;
            float t0 = acc[i][j4 * 4 + 0];
            float t1 = acc[i][j4 * 4 + 1];
            float t2 = acc[i][j4 * 4 + 2];
            float t3 = acc[i][j4 * 4 + 3];
            if (MODE == 1) {  // ELU
                t0 = t0 > 0.f ? t0 : (expf(t0) - 1.f);
                t1 = t1 > 0.f ? t1 : (expf(t1) - 1.f);
                t2 = t2 > 0.f ? t2 : (expf(t2) - 1.f);
                t3 = t3 > 0.f ? t3 : (expf(t3) - 1.f);
            }
            v.x = t0; v.y = t1; v.z = t2; v.w = t3;
            *reinterpret_cast<float4*>(crow + j4 * 4) = v;
        }
    }
}

// ---------------------------------------------------------------------------
// K3: s_src/s_dst = h . a_src / a_dst.  One warp per (be, n) row.
// ---------------------------------------------------------------------------
__global__ void k_scores(const float* __restrict__ ASRC,
                         const float* __restrict__ ADST) {
    int row = blockIdx.x * 8 + (threadIdx.x >> 5);  // be*N + n
    int lane = threadIdx.x & 31;
    if (row >= BB * EE * NN) return;
    int e = (row / NN) & 7;

    const float* hr = g_h + (size_t)row * DD;
    const float* as = ASRC + (size_t)e * DD;
    const float* ad = ADST + (size_t)e * DD;
    float s = 0.f, d = 0.f;
    for (int z = lane; z < DD; z += 32) {
        float hv = hr[z];
        s = fmaf(hv, as[z], s);
        d = fmaf(hv, ad[z], d);
    }
#pragma unroll
    for (int off = 16; off > 0; off >>= 1) {
        s += __shfl_xor_sync(0xFFFFFFFFu, s, off);
        d += __shfl_xor_sync(0xFFFFFFFFu, d, off);
    }
    if (lane == 0) {
        g_ssrc[row] = s;
        g_sdst[row] = d;
    }
}

// ---------------------------------------------------------------------------
// K4: attention softmax rows.  Block = 8 warps; warp w handles row i0+w of
// one (b,e).  scores in smem, two-pass max/sum, write normalized attn.
// ---------------------------------------------------------------------------
__global__ void __launch_bounds__(256) k_attn(const int* __restrict__ ADJ) {
    const int be = blockIdx.x >> 7;            // 128 blocks per (b,e)
    const int i0 = (blockIdx.x & 127) * 8;
    const int b = be >> 3;
    const int tid = threadIdx.x;
    const int w = tid >> 5;
    const int lane = tid & 31;

    __shared__ float sdst[NN];
    __shared__ float sc[8][NN];

    for (int j = tid; j < NN; j += 256) sdst[j] = g_sdst[(size_t)be * NN + j];
    __syncthreads();

    const int i = i0 + w;
    const float ssrc = g_ssrc[(size_t)be * NN + i];
    const int* adjrow = ADJ + ((size_t)b * NN + i) * NN;

    float m = -3.4e38f;
    for (int j = lane; j < NN; j += 32) {
        int a = adjrow[j];
        float s = ssrc + sdst[j];
        s = s > 0.f ? s : SLOPE * s;
        s = a ? s : NEGV;
        sc[w][j] = s;
        m = fmaxf(m, s);
    }
#pragma unroll
    for (int off = 16; off > 0; off >>= 1)
        m = fmaxf(m, __shfl_xor_sync(0xFFFFFFFFu, m, off));

    float sum = 0.f;
    for (int j = lane; j < NN; j += 32) {
        float p = expf(sc[w][j] - m);
        sc[w][j] = p;
        sum += p;
    }
#pragma unroll
    for (int off = 16; off > 0; off >>= 1)
        sum += __shfl_xor_sync(0xFFFFFFFFu, sum, off);

    float inv = 1.0f / sum;
    float* arow = g_attn + ((size_t)be * NN + i) * NN;
    for (int j = lane; j < NN; j += 32) arow[j] = sc[w][j] * inv;
}

// ---------------------------------------------------------------------------
// K6: combine  out[b,n,z] = sum_e gate[b,n,e] * oute[b,e,n,z]   (float4)
// ---------------------------------------------------------------------------
__global__ void k_combine(float* __restrict__ OUT) {
    int idx = blockIdx.x * 256 + threadIdx.x;   // over B*N*D/4
    const int D4 = DD / 4;
    if (idx >= BB * NN * D4) return;
    int z4 = idx % D4;
    int n = (idx / D4) % NN;
    int b = idx / (D4 * NN);

    const float* gr = g_gate + ((size_t)b * NN + n) * EE;
    float4 acc = make_float4(0.f, 0.f, 0.f, 0.f);
#pragma unroll
    for (int e = 0; e < EE; e++) {
        float g = gr[e];
        const float4 v = *reinterpret_cast<const float4*>(
            g_oute + (((size_t)(b * EE + e) * NN + n) * DD) + z4 * 4);
        acc.x = fmaf(g, v.x, acc.x);
        acc.y = fmaf(g, v.y, acc.y);
        acc.z = fmaf(g, v.z, acc.z);
        acc.w = fmaf(g, v.w, acc.w);
    }
    reinterpret_cast<float4*>(OUT)[idx] = acc;
}

// ---------------------------------------------------------------------------
// Launch
// ---------------------------------------------------------------------------
extern "C" void kernel_launch(void* const* d_in, const int* in_sizes, int n_in,
                              void* d_out, int out_size) {
    const float* x      = (const float*)d_in[0];
    const int*   adj    = (const int*)d_in[1];
    const float* gate_W = (const float*)d_in[2];
    const float* gate_b = (const float*)d_in[3];
    const float* W      = (const float*)d_in[4];
    const float* a_src  = (const float*)d_in[5];
    const float* a_dst  = (const float*)d_in[6];
    float* out = (float*)d_out;

    // K1: gate
    k_gate<<<BB * NN / 8, 256>>>(x, gate_W, gate_b);

    // K2: h = x @ W[e]   grid (512/128, 1024/128, 64)
    k_sgemm<0><<<dim3(DD / 128, NN / 128, BB * EE), 256>>>(x, W);

    // K3: s_src / s_dst
    k_scores<<<BB * EE * NN / 8, 256>>>(a_src, a_dst);

    // K4: attention softmax
    k_attn<<<BB * EE * (NN / 8), 256>>>(adj);

    // K5: out_e = elu(attn @ h)
    k_sgemm<1><<<dim3(DD / 128, NN / 128, BB * EE), 256>>>(nullptr, nullptr);

    // K6: combine over experts
    k_combine<<<(BB * NN * (DD / 4) + 255) / 256, 256>>>(out);
}

// round 5
// speedup vs baseline: 3.1028x; 3.1028x over previous
#include <cuda_runtime.h>
#include <stdint.h>
#include <math.h>

#define BB 8
#define NN 1024
#define DD 512
#define EE 8
#define NEGV (-1e9f)
#define SLOPE 0.2f

// ---------------------------------------------------------------------------
// Static device scratch
// ---------------------------------------------------------------------------
__device__ static float g_xr[(size_t)BB * NN * DD];      // rna(x)
__device__ static float g_wt[(size_t)EE * DD * DD];      // rna(W^T) [e][z][d]
__device__ static float g_ht[(size_t)BB * EE * DD * NN]; // rna(h^T) [be][z][j]
__device__ static float g_attn[(size_t)BB * EE * NN * NN];
__device__ static float g_oute[(size_t)BB * EE * NN * DD];
__device__ static float g_gate[(size_t)BB * NN * EE];
__device__ static float g_ssrc[(size_t)BB * EE * NN];
__device__ static float g_sdst[(size_t)BB * EE * NN];

// ---------------------------------------------------------------------------
// Helpers
// ---------------------------------------------------------------------------
__device__ __forceinline__ float f2tf32(float x) {
    uint32_t u;
    asm("cvt.rna.tf32.f32 %0, %1;" : "=r"(u) : "f"(x));
    return __uint_as_float(u);
}

__device__ __forceinline__ uint32_t smem_u32(const void* p) {
    uint32_t a;
    asm("{ .reg .u64 t; cvta.to.shared.u64 t, %1; cvt.u32.u64 %0, t; }"
        : "=r"(a) : "l"(p));
    return a;
}

#define CP16(dst, src) \
    asm volatile("cp.async.cg.shared.global [%0], [%1], 16;" :: "r"(dst), "l"(src))

#define MMA_TF32(c, a0, a1, a2, a3, b0, b1) \
    asm volatile("mma.sync.aligned.m16n8k8.row.col.f32.tf32.tf32.f32 " \
        "{%0,%1,%2,%3}, {%4,%5,%6,%7}, {%8,%9}, {%0,%1,%2,%3};" \
        : "+f"((c)[0]), "+f"((c)[1]), "+f"((c)[2]), "+f"((c)[3]) \
        : "r"(a0), "r"(a1), "r"(a2), "r"(a3), "r"(b0), "r"(b1))

__device__ __forceinline__ uint32_t sw128(uint32_t off) {
    return off ^ ((off >> 3) & 0x70);
}

// ---------------------------------------------------------------------------
// K0a: g_xr = rna(x)
// ---------------------------------------------------------------------------
__global__ void k_cvt(const float4* __restrict__ X) {
    int i = blockIdx.x * 256 + threadIdx.x;
    float4 v = X[i];
    float4 o;
    o.x = f2tf32(v.x); o.y = f2tf32(v.y); o.z = f2tf32(v.z); o.w = f2tf32(v.w);
    reinterpret_cast<float4*>(g_xr)[i] = o;
}

// K0b: g_wt[e][z][d] = rna(W[e][d][z])
__global__ void k_tw(const float* __restrict__ W) {
    __shared__ float t[32][33];
    int e = blockIdx.z;
    int x0 = blockIdx.x * 32;
    int y0 = blockIdx.y * 32;
    int tx = threadIdx.x, ty = threadIdx.y;
    const float* Wb = W + (size_t)e * DD * DD;
#pragma unroll
    for (int i = 0; i < 32; i += 8)
        t[ty + i][tx] = Wb[(size_t)(y0 + ty + i) * DD + x0 + tx];
    __syncthreads();
    float* Ob = g_wt + (size_t)e * DD * DD;
#pragma unroll
    for (int i = 0; i < 32; i += 8)
        Ob[(size_t)(x0 + ty + i) * DD + y0 + tx] = f2tf32(t[tx][ty + i]);
}

// ---------------------------------------------------------------------------
// K1: gate softmax (warp per row)
// ---------------------------------------------------------------------------
__global__ void k_gate(const float* __restrict__ X, const float* __restrict__ GW,
                       const float* __restrict__ GB) {
    int row = blockIdx.x * 8 + (threadIdx.x >> 5);
    int lane = threadIdx.x & 31;
    if (row >= BB * NN) return;
    float acc[EE];
#pragma unroll
    for (int e = 0; e < EE; e++) acc[e] = 0.f;
    const float* xr = X + (size_t)row * DD;
    for (int d = lane; d < DD; d += 32) {
        float xv = xr[d];
        const float* gw = GW + (size_t)d * EE;
#pragma unroll
        for (int e = 0; e < EE; e++) acc[e] = fmaf(xv, gw[e], acc[e]);
    }
#pragma unroll
    for (int e = 0; e < EE; e++)
#pragma unroll
        for (int off = 16; off > 0; off >>= 1)
            acc[e] += __shfl_xor_sync(0xFFFFFFFFu, acc[e], off);
    if (lane == 0) {
        float m = -3.4e38f;
#pragma unroll
        for (int e = 0; e < EE; e++) { acc[e] += GB[e]; m = fmaxf(m, acc[e]); }
        float s = 0.f;
#pragma unroll
        for (int e = 0; e < EE; e++) { acc[e] = expf(acc[e] - m); s += acc[e]; }
        float inv = 1.0f / s;
        float* gr = g_gate + (size_t)row * EE;
#pragma unroll
        for (int e = 0; e < EE; e++) gr[e] = acc[e] * inv;
    }
}

// ---------------------------------------------------------------------------
// mma.sync tf32 GEMM: CTA tile 128x128x32, 8 warps (2m x 4n), warp 64x32.
// A row-major [m][k]; B row-major-as-[n][k] (= col-major kxn).
// MODE 0: C = xr[b] @ wt[e]^T      (K=512)  -> g_ht transposed (rna)
// MODE 1: C = elu(attn @ ht^T)     (K=1024) -> g_oute row-major
// ---------------------------------------------------------------------------
#define BM 128
#define BN 128
#define BK 32

template <int MODE>
__global__ void __launch_bounds__(256) k_mma() {
    constexpr int K = (MODE == 0) ? DD : NN;
    constexpr int S = K / BK;

    extern __shared__ char smem[];
    const uint32_t sb = smem_u32(smem);

    const int tid = threadIdx.x;
    const int wid = tid >> 5;
    const int lane = tid & 31;
    const int q = lane >> 2;        // 0..7
    const int t4 = lane & 3;        // 0..3
    const int warpM = (wid & 1) * 64;
    const int warpN = (wid >> 1) * 32;

    const int be = blockIdx.z;
    const int rowBase = blockIdx.y * BM;
    const int colBase = blockIdx.x * BN;

    const float* Ab;
    const float* Bb;
    if (MODE == 0) {
        Ab = g_xr + (size_t)(be >> 3) * NN * DD;
        Bb = g_wt + (size_t)(be & 7) * DD * DD;
    } else {
        Ab = g_attn + (size_t)be * NN * NN;
        Bb = g_ht + (size_t)be * DD * NN;
    }

    float c[4][4][4];
#pragma unroll
    for (int mi = 0; mi < 4; mi++)
#pragma unroll
        for (int ni = 0; ni < 4; ni++)
#pragma unroll
            for (int k = 0; k < 4; k++) c[mi][ni][k] = 0.f;

    // double-buffered loader: A at sb + buf*16384, B at sb+32768 + buf*16384
    auto load_stage = [&](int s) {
        const uint32_t ab = sb + (s & 1) * 16384;
        const uint32_t bb = sb + 32768 + (s & 1) * 16384;
        const int k0 = s * BK;
#pragma unroll
        for (int i = 0; i < 4; i++) {
            int id = tid + i * 256;                 // 1024 chunks of 16B
            int r = id >> 3;
            int ch = (id & 7) * 16;
            CP16(ab + sw128((uint32_t)(r * 128 + ch)),
                 Ab + (size_t)(rowBase + r) * K + k0 + (ch >> 2));
        }
#pragma unroll
        for (int i = 0; i < 4; i++) {
            int id = tid + i * 256;
            int r = id >> 3;
            int ch = (id & 7) * 16;
            CP16(bb + sw128((uint32_t)(r * 128 + ch)),
                 Bb + (size_t)(colBase + r) * K + k0 + (ch >> 2));
        }
        asm volatile("cp.async.commit_group;" ::: "memory");
    };

    load_stage(0);
    for (int s = 0; s < S; s++) {
        if (s + 1 < S) {
            load_stage(s + 1);
            asm volatile("cp.async.wait_group 1;" ::: "memory");
        } else {
            asm volatile("cp.async.wait_group 0;" ::: "memory");
        }
        __syncthreads();

        const uint32_t* A32 =
            reinterpret_cast<const uint32_t*>(smem + (s & 1) * 16384);
        const uint32_t* B32 =
            reinterpret_cast<const uint32_t*>(smem + 32768 + (s & 1) * 16384);

        // swizzled word index: row*32 + t4 + 4*(t ^ q), t = k16-chunk index
#pragma unroll
        for (int j = 0; j < 4; j++) {
            uint32_t bf[4][2];
#pragma unroll
            for (int ni = 0; ni < 4; ni++) {
                int nr = warpN + 8 * ni + q;
                bf[ni][0] = B32[nr * 32 + t4 + 4 * ((2 * j) ^ q)];
                bf[ni][1] = B32[nr * 32 + t4 + 4 * ((2 * j + 1) ^ q)];
            }
#pragma unroll
            for (int mi = 0; mi < 4; mi++) {
                int mr = warpM + 16 * mi + q;
                uint32_t a0 = A32[mr * 32 + t4 + 4 * ((2 * j) ^ q)];
                uint32_t a1 = A32[(mr + 8) * 32 + t4 + 4 * ((2 * j) ^ q)];
                uint32_t a2 = A32[mr * 32 + t4 + 4 * ((2 * j + 1) ^ q)];
                uint32_t a3 = A32[(mr + 8) * 32 + t4 + 4 * ((2 * j + 1) ^ q)];
#pragma unroll
                for (int ni = 0; ni < 4; ni++)
                    MMA_TF32(c[mi][ni], a0, a1, a2, a3, bf[ni][0], bf[ni][1]);
            }
        }
        __syncthreads();
    }

    // ---- epilogue: direct fragment stores (32B-sector coalesced) ----
    if (MODE == 0) {
        float* htb = g_ht + (size_t)be * DD * NN;
#pragma unroll
        for (int mi = 0; mi < 4; mi++) {
            int r0 = rowBase + warpM + 16 * mi + q;
#pragma unroll
            for (int ni = 0; ni < 4; ni++) {
                int c0 = colBase + warpN + 8 * ni + 2 * t4;
                htb[(size_t)c0 * NN + r0]           = f2tf32(c[mi][ni][0]);
                htb[(size_t)(c0 + 1) * NN + r0]     = f2tf32(c[mi][ni][1]);
                htb[(size_t)c0 * NN + r0 + 8]       = f2tf32(c[mi][ni][2]);
                htb[(size_t)(c0 + 1) * NN + r0 + 8] = f2tf32(c[mi][ni][3]);
            }
        }
    } else {
        float* ob = g_oute + (size_t)be * NN * DD;
#pragma unroll
        for (int mi = 0; mi < 4; mi++) {
            int r0 = rowBase + warpM + 16 * mi + q;
#pragma unroll
            for (int ni = 0; ni < 4; ni++) {
                int c0 = colBase + warpN + 8 * ni + 2 * t4;
                float v0 = c[mi][ni][0], v1 = c[mi][ni][1];
                float v2 = c[mi][ni][2], v3 = c[mi][ni][3];
                v0 = v0 > 0.f ? v0 : expm1f(v0);
                v1 = v1 > 0.f ? v1 : expm1f(v1);
                v2 = v2 > 0.f ? v2 : expm1f(v2);
                v3 = v3 > 0.f ? v3 : expm1f(v3);
                *reinterpret_cast<float2*>(&ob[(size_t)r0 * DD + c0]) =
                    make_float2(v0, v1);
                *reinterpret_cast<float2*>(&ob[(size_t)(r0 + 8) * DD + c0]) =
                    make_float2(v2, v3);
            }
        }
    }
}

// ---------------------------------------------------------------------------
// K3: scores from h^T (coalesced over n)
// ---------------------------------------------------------------------------
__global__ void __launch_bounds__(256) k_scores(const float* __restrict__ ASRC,
                                                const float* __restrict__ ADST) {
    __shared__ float sa[DD], sd[DD];
    const int be = blockIdx.x >> 2;
    const int n0 = (blockIdx.x & 3) * 256;
    const int e = be & 7;
    const int tid = threadIdx.x;
    for (int z = tid; z < DD; z += 256) {
        sa[z] = ASRC[(size_t)e * DD + z];
        sd[z] = ADST[(size_t)e * DD + z];
    }
    __syncthreads();
    const float* htb = g_ht + (size_t)be * DD * NN + n0 + tid;
    float s = 0.f, d = 0.f;
    for (int z = 0; z < DD; z++) {
        float h = htb[(size_t)z * NN];
        s = fmaf(h, sa[z], s);
        d = fmaf(h, sd[z], d);
    }
    g_ssrc[(size_t)be * NN + n0 + tid] = s;
    g_sdst[(size_t)be * NN + n0 + tid] = d;
}

// ---------------------------------------------------------------------------
// K4: attention softmax (writes rna'd attn)
// ---------------------------------------------------------------------------
__global__ void __launch_bounds__(256) k_attn(const int* __restrict__ ADJ) {
    const int be = blockIdx.x >> 7;
    const int i0 = (blockIdx.x & 127) * 8;
    const int b = be >> 3;
    const int tid = threadIdx.x;
    const int w = tid >> 5;
    const int lane = tid & 31;

    __shared__ float sdst[NN];
    __shared__ float sc[8][NN];

    for (int j = tid; j < NN; j += 256) sdst[j] = g_sdst[(size_t)be * NN + j];
    __syncthreads();

    const int i = i0 + w;
    const float ssrc = g_ssrc[(size_t)be * NN + i];
    const int* adjrow = ADJ + ((size_t)b * NN + i) * NN;

    float m = -3.4e38f;
    for (int j = lane; j < NN; j += 32) {
        int a = adjrow[j];
        float s = ssrc + sdst[j];
        s = s > 0.f ? s : SLOPE * s;
        s = a ? s : NEGV;
        sc[w][j] = s;
        m = fmaxf(m, s);
    }
#pragma unroll
    for (int off = 16; off > 0; off >>= 1)
        m = fmaxf(m, __shfl_xor_sync(0xFFFFFFFFu, m, off));

    float sum = 0.f;
    for (int j = lane; j < NN; j += 32) {
        float p = expf(sc[w][j] - m);
        sc[w][j] = p;
        sum += p;
    }
#pragma unroll
    for (int off = 16; off > 0; off >>= 1)
        sum += __shfl_xor_sync(0xFFFFFFFFu, sum, off);

    float inv = 1.0f / sum;
    float* arow = g_attn + ((size_t)be * NN + i) * NN;
    for (int j = lane; j < NN; j += 32) arow[j] = f2tf32(sc[w][j] * inv);
}

// ---------------------------------------------------------------------------
// K6: combine over experts
// ---------------------------------------------------------------------------
__global__ void k_combine(float* __restrict__ OUT) {
    int idx = blockIdx.x * 256 + threadIdx.x;
    const int D4 = DD / 4;
    if (idx >= BB * NN * D4) return;
    int z4 = idx % D4;
    int n = (idx / D4) % NN;
    int b = idx / (D4 * NN);

    const float* gr = g_gate + ((size_t)b * NN + n) * EE;
    float4 acc = make_float4(0.f, 0.f, 0.f, 0.f);
#pragma unroll
    for (int e = 0; e < EE; e++) {
        float g = gr[e];
        const float4 v = *reinterpret_cast<const float4*>(
            g_oute + (((size_t)(b * EE + e) * NN + n) * DD) + z4 * 4);
        acc.x = fmaf(g, v.x, acc.x);
        acc.y = fmaf(g, v.y, acc.y);
        acc.z = fmaf(g, v.z, acc.z);
        acc.w = fmaf(g, v.w, acc.w);
    }
    reinterpret_cast<float4*>(OUT)[idx] = acc;
}

// ---------------------------------------------------------------------------
// Launch
// ---------------------------------------------------------------------------
extern "C" void kernel_launch(void* const* d_in, const int* in_sizes, int n_in,
                              void* d_out, int out_size) {
    const float* x      = (const float*)d_in[0];
    const int*   adj    = (const int*)d_in[1];
    const float* gate_W = (const float*)d_in[2];
    const float* gate_b = (const float*)d_in[3];
    const float* W      = (const float*)d_in[4];
    const float* a_src  = (const float*)d_in[5];
    const float* a_dst  = (const float*)d_in[6];
    float* out = (float*)d_out;

    const int SMEM = 65536;
    cudaFuncSetAttribute(k_mma<0>, cudaFuncAttributeMaxDynamicSharedMemorySize, SMEM);
    cudaFuncSetAttribute(k_mma<1>, cudaFuncAttributeMaxDynamicSharedMemorySize, SMEM);

    k_cvt<<<BB * NN * DD / 4 / 256, 256>>>((const float4*)x);
    k_tw<<<dim3(16, 16, 8), dim3(32, 8)>>>(W);
    k_gate<<<BB * NN / 8, 256>>>(x, gate_W, gate_b);

    k_mma<0><<<dim3(DD / BN, NN / BM, BB * EE), 256, SMEM>>>();

    k_scores<<<64 * 4, 256>>>(a_src, a_dst);
    k_attn<<<BB * EE * (NN / 8), 256>>>(adj);

    k_mma<1><<<dim3(DD / BN, NN / BM, BB * EE), 256, SMEM>>>();

    k_combine<<<(BB * NN * (DD / 4) + 255) / 256, 256>>>(out);
}

// round 7
// speedup vs baseline: 3.1771x; 1.0239x over previous
#include <cuda_runtime.h>
#include <stdint.h>
#include <math.h>

#define BB 8
#define NN 1024
#define DD 512
#define EE 8
#define NEGV (-1e9f)
#define SLOPE 0.2f

// ---------------------------------------------------------------------------
// Static device scratch
// ---------------------------------------------------------------------------
__device__ static float g_xr[(size_t)BB * NN * DD];      // rna(x)
__device__ static float g_wt[(size_t)EE * DD * DD];      // rna(W^T) [e][z][d]
__device__ static float g_ht[(size_t)BB * EE * DD * NN]; // rna(h^T) [be][z][j]
__device__ static float g_attn[(size_t)BB * EE * NN * NN];
__device__ static float g_oute[(size_t)BB * EE * NN * DD];
__device__ static float g_gate[(size_t)BB * NN * EE];
__device__ static float g_ssrc[(size_t)BB * EE * NN];
__device__ static float g_sdst[(size_t)BB * EE * NN];

// ---------------------------------------------------------------------------
// Helpers
// ---------------------------------------------------------------------------
__device__ __forceinline__ float f2tf32(float x) {
    uint32_t u;
    asm("cvt.rna.tf32.f32 %0, %1;" : "=r"(u) : "f"(x));
    return __uint_as_float(u);
}

__device__ __forceinline__ uint32_t smem_u32(const void* p) {
    uint32_t a;
    asm("{ .reg .u64 t; cvta.to.shared.u64 t, %1; cvt.u32.u64 %0, t; }"
        : "=r"(a) : "l"(p));
    return a;
}

#define CP16(dst, src) \
    asm volatile("cp.async.cg.shared.global [%0], [%1], 16;" :: "r"(dst), "l"(src))

#define MMA_TF32(c, a0, a1, a2, a3, b0, b1) \
    asm volatile("mma.sync.aligned.m16n8k8.row.col.f32.tf32.tf32.f32 " \
        "{%0,%1,%2,%3}, {%4,%5,%6,%7}, {%8,%9}, {%0,%1,%2,%3};" \
        : "+f"((c)[0]), "+f"((c)[1]), "+f"((c)[2]), "+f"((c)[3]) \
        : "r"(a0), "r"(a1), "r"(a2), "r"(a3), "r"(b0), "r"(b1))

__device__ __forceinline__ uint32_t sw128(uint32_t off) {
    return off ^ ((off >> 3) & 0x70);
}

// ---------------------------------------------------------------------------
// K0a: g_xr = rna(x)
// ---------------------------------------------------------------------------
__global__ void k_cvt(const float4* __restrict__ X) {
    int i = blockIdx.x * 256 + threadIdx.x;
    float4 v = X[i];
    float4 o;
    o.x = f2tf32(v.x); o.y = f2tf32(v.y); o.z = f2tf32(v.z); o.w = f2tf32(v.w);
    reinterpret_cast<float4*>(g_xr)[i] = o;
}

// K0b: g_wt[e][z][d] = rna(W[e][d][z])
__global__ void k_tw(const float* __restrict__ W) {
    __shared__ float t[32][33];
    int e = blockIdx.z;
    int x0 = blockIdx.x * 32;
    int y0 = blockIdx.y * 32;
    int tx = threadIdx.x, ty = threadIdx.y;
    const float* Wb = W + (size_t)e * DD * DD;
#pragma unroll
    for (int i = 0; i < 32; i += 8)
        t[ty + i][tx] = Wb[(size_t)(y0 + ty + i) * DD + x0 + tx];
    __syncthreads();
    float* Ob = g_wt + (size_t)e * DD * DD;
#pragma unroll
    for (int i = 0; i < 32; i += 8)
        Ob[(size_t)(x0 + ty + i) * DD + y0 + tx] = f2tf32(t[tx][ty + i]);
}

// ---------------------------------------------------------------------------
// K1: gate softmax (warp per row)
// ---------------------------------------------------------------------------
__global__ void k_gate(const float* __restrict__ X, const float* __restrict__ GW,
                       const float* __restrict__ GB) {
    int row = blockIdx.x * 8 + (threadIdx.x >> 5);
    int lane = threadIdx.x & 31;
    if (row >= BB * NN) return;
    float acc[EE];
#pragma unroll
    for (int e = 0; e < EE; e++) acc[e] = 0.f;
    const float* xr = X + (size_t)row * DD;
    for (int d = lane; d < DD; d += 32) {
        float xv = xr[d];
        const float* gw = GW + (size_t)d * EE;
#pragma unroll
        for (int e = 0; e < EE; e++) acc[e] = fmaf(xv, gw[e], acc[e]);
    }
#pragma unroll
    for (int e = 0; e < EE; e++)
#pragma unroll
        for (int off = 16; off > 0; off >>= 1)
            acc[e] += __shfl_xor_sync(0xFFFFFFFFu, acc[e], off);
    if (lane == 0) {
        float m = -3.4e38f;
#pragma unroll
        for (int e = 0; e < EE; e++) { acc[e] += GB[e]; m = fmaxf(m, acc[e]); }
        float s = 0.f;
#pragma unroll
        for (int e = 0; e < EE; e++) { acc[e] = expf(acc[e] - m); s += acc[e]; }
        float inv = 1.0f / s;
        float* gr = g_gate + (size_t)row * EE;
#pragma unroll
        for (int e = 0; e < EE; e++) gr[e] = acc[e] * inv;
    }
}

// ---------------------------------------------------------------------------
// mma.sync tf32 GEMM: CTA tile 128x128x32, 4 warps (2m x 2n), warp 64x64.
// A row-major [m][k]; B row-major-as-[n][k] (= col-major kxn).
// MODE 0: C = xr[b] @ wt[e]^T      (K=512)  -> g_ht transposed (rna)
// MODE 1: C = elu(attn @ ht^T)     (K=1024) -> g_oute row-major
// ---------------------------------------------------------------------------
#define BM 128
#define BN 128
#define BK 32

template <int MODE>
__global__ void __launch_bounds__(128, 2) k_mma() {
    constexpr int K = (MODE == 0) ? DD : NN;
    constexpr int S = K / BK;

    extern __shared__ char smem[];
    const uint32_t sb = smem_u32(smem);

    const int tid = threadIdx.x;
    const int wid = tid >> 5;
    const int lane = tid & 31;
    const int q = lane >> 2;        // 0..7
    const int t4 = lane & 3;        // 0..3
    const int warpM = (wid & 1) * 64;
    const int warpN = (wid >> 1) * 64;

    const int be = blockIdx.z;
    const int rowBase = blockIdx.y * BM;
    const int colBase = blockIdx.x * BN;

    const float* Ab;
    const float* Bb;
    if (MODE == 0) {
        Ab = g_xr + (size_t)(be >> 3) * NN * DD;
        Bb = g_wt + (size_t)(be & 7) * DD * DD;
    } else {
        Ab = g_attn + (size_t)be * NN * NN;
        Bb = g_ht + (size_t)be * DD * NN;
    }

    float c[4][8][4];
#pragma unroll
    for (int mi = 0; mi < 4; mi++)
#pragma unroll
        for (int ni = 0; ni < 8; ni++)
#pragma unroll
            for (int k = 0; k < 4; k++) c[mi][ni][k] = 0.f;

    // double-buffered loader: A at sb + buf*16384, B at sb+32768 + buf*16384
    auto load_stage = [&](int s) {
        const uint32_t ab = sb + (s & 1) * 16384;
        const uint32_t bb = sb + 32768 + (s & 1) * 16384;
        const int k0 = s * BK;
#pragma unroll
        for (int i = 0; i < 8; i++) {
            int id = tid + i * 128;                 // 1024 chunks of 16B
            int r = id >> 3;
            int ch = (id & 7) * 16;
            CP16(ab + sw128((uint32_t)(r * 128 + ch)),
                 Ab + (size_t)(rowBase + r) * K + k0 + (ch >> 2));
        }
#pragma unroll
        for (int i = 0; i < 8; i++) {
            int id = tid + i * 128;
            int r = id >> 3;
            int ch = (id & 7) * 16;
            CP16(bb + sw128((uint32_t)(r * 128 + ch)),
                 Bb + (size_t)(colBase + r) * K + k0 + (ch >> 2));
        }
        asm volatile("cp.async.commit_group;" ::: "memory");
    };

    load_stage(0);
    for (int s = 0; s < S; s++) {
        if (s + 1 < S) {
            load_stage(s + 1);
            asm volatile("cp.async.wait_group 1;" ::: "memory");
        } else {
            asm volatile("cp.async.wait_group 0;" ::: "memory");
        }
        __syncthreads();

        const uint32_t* A32 =
            reinterpret_cast<const uint32_t*>(smem + (s & 1) * 16384);
        const uint32_t* B32 =
            reinterpret_cast<const uint32_t*>(smem + 32768 + (s & 1) * 16384);

        // swizzled word index: row*32 + t4 + 4*(t ^ q), t = k16-chunk index
#pragma unroll
        for (int j = 0; j < 4; j++) {
            uint32_t bf[8][2];
#pragma unroll
            for (int ni = 0; ni < 8; ni++) {
                int nr = warpN + 8 * ni + q;
                bf[ni][0] = B32[nr * 32 + t4 + 4 * ((2 * j) ^ q)];
                bf[ni][1] = B32[nr * 32 + t4 + 4 * ((2 * j + 1) ^ q)];
            }
#pragma unroll
            for (int mi = 0; mi < 4; mi++) {
                int mr = warpM + 16 * mi + q;
                uint32_t a0 = A32[mr * 32 + t4 + 4 * ((2 * j) ^ q)];
                uint32_t a1 = A32[(mr + 8) * 32 + t4 + 4 * ((2 * j) ^ q)];
                uint32_t a2 = A32[mr * 32 + t4 + 4 * ((2 * j + 1) ^ q)];
                uint32_t a3 = A32[(mr + 8) * 32 + t4 + 4 * ((2 * j + 1) ^ q)];
#pragma unroll
                for (int ni = 0; ni < 8; ni++)
                    MMA_TF32(c[mi][ni], a0, a1, a2, a3, bf[ni][0], bf[ni][1]);
            }
        }
        __syncthreads();
    }

    // ---- epilogue: direct fragment stores (32B-sector coalesced) ----
    if (MODE == 0) {
        float* htb = g_ht + (size_t)be * DD * NN;
#pragma unroll
        for (int mi = 0; mi < 4; mi++) {
            int r0 = rowBase + warpM + 16 * mi + q;
#pragma unroll
            for (int ni = 0; ni < 8; ni++) {
                int c0 = colBase + warpN + 8 * ni + 2 * t4;
                htb[(size_t)c0 * NN + r0]           = f2tf32(c[mi][ni][0]);
                htb[(size_t)(c0 + 1) * NN + r0]     = f2tf32(c[mi][ni][1]);
                htb[(size_t)c0 * NN + r0 + 8]       = f2tf32(c[mi][ni][2]);
                htb[(size_t)(c0 + 1) * NN + r0 + 8] = f2tf32(c[mi][ni][3]);
            }
        }
    } else {
        float* ob = g_oute + (size_t)be * NN * DD;
#pragma unroll
        for (int mi = 0; mi < 4; mi++) {
            int r0 = rowBase + warpM + 16 * mi + q;
#pragma unroll
            for (int ni = 0; ni < 8; ni++) {
                int c0 = colBase + warpN + 8 * ni + 2 * t4;
                float v0 = c[mi][ni][0], v1 = c[mi][ni][1];
                float v2 = c[mi][ni][2], v3 = c[mi][ni][3];
                v0 = v0 > 0.f ? v0 : expm1f(v0);
                v1 = v1 > 0.f ? v1 : expm1f(v1);
                v2 = v2 > 0.f ? v2 : expm1f(v2);
                v3 = v3 > 0.f ? v3 : expm1f(v3);
                *reinterpret_cast<float2*>(&ob[(size_t)r0 * DD + c0]) =
                    make_float2(v0, v1);
                *reinterpret_cast<float2*>(&ob[(size_t)(r0 + 8) * DD + c0]) =
                    make_float2(v2, v3);
            }
        }
    }
}

// ---------------------------------------------------------------------------
// K3: scores from h^T (coalesced over n)
// ---------------------------------------------------------------------------
__global__ void __launch_bounds__(256) k_scores(const float* __restrict__ ASRC,
                                                const float* __restrict__ ADST) {
    __shared__ float sa[DD], sd[DD];
    const int be = blockIdx.x >> 2;
    const int n0 = (blockIdx.x & 3) * 256;
    const int e = be & 7;
    const int tid = threadIdx.x;
    for (int z = tid; z < DD; z += 256) {
        sa[z] = ASRC[(size_t)e * DD + z];
        sd[z] = ADST[(size_t)e * DD + z];
    }
    __syncthreads();
    const float* htb = g_ht + (size_t)be * DD * NN + n0 + tid;
    float s = 0.f, d = 0.f;
    for (int z = 0; z < DD; z++) {
        float h = htb[(size_t)z * NN];
        s = fmaf(h, sa[z], s);
        d = fmaf(h, sd[z], d);
    }
    g_ssrc[(size_t)be * NN + n0 + tid] = s;
    g_sdst[(size_t)be * NN + n0 + tid] = d;
}

// ---------------------------------------------------------------------------
// K4: attention softmax (writes rna'd attn)
// ---------------------------------------------------------------------------
__global__ void __launch_bounds__(256) k_attn(const int* __restrict__ ADJ) {
    const int be = blockIdx.x >> 7;
    const int i0 = (blockIdx.x & 127) * 8;
    const int b = be >> 3;
    const int tid = threadIdx.x;
    const int w = tid >> 5;
    const int lane = tid & 31;

    __shared__ float sdst[NN];
    __shared__ float sc[8][NN];

    for (int j = tid; j < NN; j += 256) sdst[j] = g_sdst[(size_t)be * NN + j];
    __syncthreads();

    const int i = i0 + w;
    const float ssrc = g_ssrc[(size_t)be * NN + i];
    const int* adjrow = ADJ + ((size_t)b * NN + i) * NN;

    float m = -3.4e38f;
    for (int j = lane; j < NN; j += 32) {
        int a = adjrow[j];
        float s = ssrc + sdst[j];
        s = s > 0.f ? s : SLOPE * s;
        s = a ? s : NEGV;
        sc[w][j] = s;
        m = fmaxf(m, s);
    }
#pragma unroll
    for (int off = 16; off > 0; off >>= 1)
        m = fmaxf(m, __shfl_xor_sync(0xFFFFFFFFu, m, off));

    float sum = 0.f;
    for (int j = lane; j < NN; j += 32) {
        float p = expf(sc[w][j] - m);
        sc[w][j] = p;
        sum += p;
    }
#pragma unroll
    for (int off = 16; off > 0; off >>= 1)
        sum += __shfl_xor_sync(0xFFFFFFFFu, sum, off);

    float inv = 1.0f / sum;
    float* arow = g_attn + ((size_t)be * NN + i) * NN;
    for (int j = lane; j < NN; j += 32) arow[j] = f2tf32(sc[w][j] * inv);
}

// ---------------------------------------------------------------------------
// K6: combine over experts
// ---------------------------------------------------------------------------
__global__ void k_combine(float* __restrict__ OUT) {
    int idx = blockIdx.x * 256 + threadIdx.x;
    const int D4 = DD / 4;
    if (idx >= BB * NN * D4) return;
    int z4 = idx % D4;
    int n = (idx / D4) % NN;
    int b = idx / (D4 * NN);

    const float* gr = g_gate + ((size_t)b * NN + n) * EE;
    float4 acc = make_float4(0.f, 0.f, 0.f, 0.f);
#pragma unroll
    for (int e = 0; e < EE; e++) {
        float g = gr[e];
        const float4 v = *reinterpret_cast<const float4*>(
            g_oute + (((size_t)(b * EE + e) * NN + n) * DD) + z4 * 4);
        acc.x = fmaf(g, v.x, acc.x);
        acc.y = fmaf(g, v.y, acc.y);
        acc.z = fmaf(g, v.z, acc.z);
        acc.w = fmaf(g, v.w, acc.w);
    }
    reinterpret_cast<float4*>(OUT)[idx] = acc;
}

// ---------------------------------------------------------------------------
// Launch
// ---------------------------------------------------------------------------
extern "C" void kernel_launch(void* const* d_in, const int* in_sizes, int n_in,
                              void* d_out, int out_size) {
    const float* x      = (const float*)d_in[0];
    const int*   adj    = (const int*)d_in[1];
    const float* gate_W = (const float*)d_in[2];
    const float* gate_b = (const float*)d_in[3];
    const float* W      = (const float*)d_in[4];
    const float* a_src  = (const float*)d_in[5];
    const float* a_dst  = (const float*)d_in[6];
    float* out = (float*)d_out;

    const int SMEM = 65536;
    cudaFuncSetAttribute(k_mma<0>, cudaFuncAttributeMaxDynamicSharedMemorySize, SMEM);
    cudaFuncSetAttribute(k_mma<1>, cudaFuncAttributeMaxDynamicSharedMemorySize, SMEM);

    k_cvt<<<BB * NN * DD / 4 / 256, 256>>>((const float4*)x);
    k_tw<<<dim3(16, 16, 8), dim3(32, 8)>>>(W);
    k_gate<<<BB * NN / 8, 256>>>(x, gate_W, gate_b);

    k_mma<0><<<dim3(DD / BN, NN / BM, BB * EE), 128, SMEM>>>();

    k_scores<<<64 * 4, 256>>>(a_src, a_dst);
    k_attn<<<BB * EE * (NN / 8), 256>>>(adj);

    k_mma<1><<<dim3(DD / BN, NN / BM, BB * EE), 128, SMEM>>>();

    k_combine<<<(BB * NN * (DD / 4) + 255) / 256, 256>>>(out);
}